// round 8
// baseline (speedup 1.0000x reference)
#include <cuda_runtime.h>
#include <cuda_fp16.h>
#include <math.h>
#include <stdint.h>

#define T_STEPS 64
#define BATCH   256
#define NCTA    444
typedef __half f16;

__device__ __forceinline__ uint32_t smem_u32(const void* p) {
    uint32_t a;
    asm("{ .reg .u64 t; cvta.to.shared.u64 t, %1; cvt.u32.u64 %0, t; }" : "=r"(a) : "l"(p));
    return a;
}
__device__ __forceinline__ void cp16(uint32_t dst, const void* src) {
    asm volatile("cp.async.cg.shared.global [%0], [%1], 16;" :: "r"(dst), "l"(src));
}
#define CP_COMMIT() asm volatile("cp.async.commit_group;" ::: "memory")
#define CP_WAIT2()  asm volatile("cp.async.wait_group 2;" ::: "memory")

__device__ __forceinline__ void ldsm4(uint32_t* r, uint32_t addr) {
    asm volatile("ldmatrix.sync.aligned.m8n8.x4.shared.b16 {%0,%1,%2,%3}, [%4];"
                 : "=r"(r[0]), "=r"(r[1]), "=r"(r[2]), "=r"(r[3]) : "r"(addr));
}
__device__ __forceinline__ void mma16816(float* c, const uint32_t* a, uint32_t b0, uint32_t b1) {
    asm volatile("mma.sync.aligned.m16n8k16.row.col.f32.f16.f16.f32 "
                 "{%0,%1,%2,%3}, {%4,%5,%6,%7}, {%8,%9}, {%0,%1,%2,%3};"
                 : "+f"(c[0]), "+f"(c[1]), "+f"(c[2]), "+f"(c[3])
                 : "r"(a[0]), "r"(a[1]), "r"(a[2]), "r"(a[3]), "r"(b0), "r"(b1));
}

// ============ scratch ============
__device__ float g_Aproj[T_STEPS * BATCH * 1024];
__device__ float g_Oproj[T_STEPS * BATCH * 1024];
__device__ float g_Wbig[2048 * 3072];
__device__ float g_bfold[3072];
__device__ float g_G[BATCH * 3072];
__device__ float g_lg[BATCH * 2048];
__device__ float g_tmp[BATCH * 1024];
__device__ float g_bstate[BATCH * 1024];
__device__ unsigned g_bar_count;
__device__ unsigned g_bar_gen;
__device__ f16 g_obs0[T_STEPS * BATCH * 1024], g_obs1[T_STEPS * BATCH * 1024];
__device__ f16 g_Wo1T0[1024 * 1024], g_Wo1T1[1024 * 1024];
__device__ f16 g_WbT0[3072 * 2048], g_WbT1[3072 * 2048];
__device__ f16 g_WcT0[2048 * 1024], g_WcT1[2048 * 1024];
__device__ f16 g_WlT0[2048 * 1024], g_WlT1[2048 * 1024];
__device__ f16 g_Ahb0[BATCH * 2048], g_Ahb1[BATCH * 2048];
__device__ f16 g_hq0[BATCH * 2048], g_hq1[BATCH * 2048];

__device__ __forceinline__ float siluf(float x) { return x / (1.0f + expf(-x)); }
__device__ __forceinline__ float sigm(float x)  { return 1.0f / (1.0f + expf(-x)); }
__device__ __forceinline__ void split2(float v, f16& h, f16& l) {
    h = __float2half_rn(v);
    l = __float2half_rn(v - __half2float(h));
}

#define STG 18432
#define TG_DSMEM (4 * STG)

// ============ GEMM tile body (device) ============
// D[M,N] = A[M,K] @ WT[N,K]^T, fp16 2-way split, 3 terms (hh, hl, lh).
// Tile 64x64, 4 warps (2x2), BK=64, 4-stage cp.async, 1 sync/iter.
// MODE 0: Cf = D + biasp[n]; if bias2 && bn>=1024: A+=1024, biasp=bias2-1024.
// MODE 3: silu(D + (bn<1024 ? bias[n] : aux[m, n-1024])) -> split2 to C0/C1.
template <int MODE>
__device__ __forceinline__ void gemm_phase(
    const f16* __restrict__ A0c, const f16* __restrict__ A1c, int lda,
    const f16* __restrict__ W0c, const f16* __restrict__ W1c, int K,
    float* __restrict__ Cf, f16* __restrict__ C0, f16* __restrict__ C1, int ldc,
    const float* __restrict__ bias, const float* __restrict__ bias2,
    const float* __restrict__ aux, int nbx, char* smem) {
    const uint32_t sb = smem_u32(smem);
    const int tid = threadIdx.x, wid = tid >> 5, lane = tid & 31;
    const int nk = K >> 6, NIT = 3 * nk;
    const int tA[3] = {0, 0, 1};
    const int tB[3] = {0, 1, 0};
    const int lr = tid >> 3, lc = tid & 7;
    const int wm = (wid >> 1) * 32, wn = (wid & 1) * 32;

    uint32_t aoff[2], boff[2];
#pragma unroll
    for (int mt = 0; mt < 2; mt++)
        aoff[mt] = (uint32_t)(wm + mt * 16 + (lane & 7) + ((lane >> 3) & 1) * 8) * 144
                 + ((lane >> 4) & 1) * 16;
#pragma unroll
    for (int np = 0; np < 2; np++)
        boff[np] = 9216 + (uint32_t)(wn + np * 16 + (lane & 7) + ((lane >> 4) & 1) * 8) * 144
                 + ((lane >> 3) & 1) * 16;

    for (int tile = blockIdx.x; tile < nbx * 4; tile += NCTA) {
        const int bn = (tile % nbx) * 64, bm = (tile / nbx) * 64;
        const f16* A0 = A0c; const f16* A1 = A1c;
        const float* biasp = bias;
        if (MODE == 0 && bias2 != nullptr && bn >= 1024) {
            A0 += 1024; A1 += 1024; biasp = bias2 - 1024;
        }
        const f16* Ap[2] = {A0 + (size_t)bm * lda, A1 + (size_t)bm * lda};
        const f16* Wp[2] = {W0c + (size_t)bn * K, W1c + (size_t)bn * K};

        float acc[2][4][4];
#pragma unroll
        for (int i = 0; i < 2; i++)
#pragma unroll
            for (int j = 0; j < 4; j++)
#pragma unroll
                for (int q = 0; q < 4; q++) acc[i][j][q] = 0.0f;

        auto issue = [&](int chunk) {
            int term = chunk / nk, kc = chunk - term * nk;
            const f16* As = Ap[tA[term]] + kc * 64;
            const f16* Ws = Wp[tB[term]] + kc * 64;
            uint32_t st = sb + (chunk & 3) * STG;
#pragma unroll
            for (int i = 0; i < 4; i++) {
                int row = lr + i * 16;
                cp16(st + row * 144 + lc * 16, As + (size_t)row * lda + lc * 8);
                cp16(st + 9216 + row * 144 + lc * 16, Ws + (size_t)row * K + lc * 8);
            }
        };

        issue(0); CP_COMMIT();
        issue(1); CP_COMMIT();
        issue(2); CP_COMMIT();

        for (int it = 0; it < NIT; it++) {
            CP_WAIT2();
            __syncthreads();
            uint32_t base = sb + (it & 3) * STG;
#pragma unroll
            for (int ks = 0; ks < 4; ks++) {
                uint32_t af[2][4], bfr[2][4];
#pragma unroll
                for (int mt = 0; mt < 2; mt++) ldsm4(af[mt], base + aoff[mt] + ks * 32);
#pragma unroll
                for (int np = 0; np < 2; np++) ldsm4(bfr[np], base + boff[np] + ks * 32);
#pragma unroll
                for (int mt = 0; mt < 2; mt++) {
#pragma unroll
                    for (int nt = 0; nt < 4; nt++)
                        mma16816(acc[mt][nt], af[mt], bfr[nt >> 1][(nt & 1) * 2],
                                 bfr[nt >> 1][(nt & 1) * 2 + 1]);
                }
            }
            if (it + 3 < NIT) issue(it + 3);
            CP_COMMIT();
        }

        const int er = lane >> 2, ec = (lane & 3) * 2;
#pragma unroll
        for (int mt = 0; mt < 2; mt++) {
#pragma unroll
            for (int nt = 0; nt < 4; nt++) {
                int m0 = bm + wm + mt * 16 + er;
                int n0 = bn + wn + nt * 8 + ec;
                float* a = acc[mt][nt];
                if (MODE == 0) {
                    float b0 = biasp[n0], b1 = biasp[n0 + 1];
                    float2 v0 = {a[0] + b0, a[1] + b1};
                    float2 v1 = {a[2] + b0, a[3] + b1};
                    *(float2*)(Cf + (size_t)m0 * ldc + n0) = v0;
                    *(float2*)(Cf + (size_t)(m0 + 8) * ldc + n0) = v1;
                } else {
                    const bool left = (bn < 1024);
#pragma unroll
                    for (int rr = 0; rr < 2; rr++) {
                        int m = m0 + rr * 8;
                        float ad0 = left ? bias[n0]     : aux[(size_t)m * 1024 + n0 - 1024];
                        float ad1 = left ? bias[n0 + 1] : aux[(size_t)m * 1024 + n0 + 1 - 1024];
                        float v0 = siluf(a[rr * 2 + 0] + ad0);
                        float v1 = siluf(a[rr * 2 + 1] + ad1);
                        f16 h0, l0, h1, l1;
                        split2(v0, h0, l0);
                        split2(v1, h1, l1);
                        *(__half2*)(C0 + (size_t)m * ldc + n0) = __halves2half2(h0, h1);
                        *(__half2*)(C1 + (size_t)m * ldc + n0) = __halves2half2(l0, l1);
                    }
                }
            }
        }
        __syncthreads();
    }
}

// ============ grid barrier ============
__device__ __forceinline__ void gbar(unsigned& gen) {
    __syncthreads();
    if (threadIdx.x == 0) {
        __threadfence();
        if (atomicAdd(&g_bar_count, 1u) == (unsigned)(NCTA - 1)) {
            g_bar_count = 0;
            __threadfence();
            *(volatile unsigned*)&g_bar_gen = gen + 1;
        } else {
            while (*(volatile unsigned*)&g_bar_gen <= gen) __nanosleep(64);
        }
    }
    __syncthreads();
    gen++;
}

__global__ void k_reset() { g_bar_count = 0; g_bar_gen = 0; }

// ============ persistent scan kernel ============
__global__ void __launch_bounds__(128, 3) k_scan(
    const f16* __restrict__ WbT0, const f16* __restrict__ WbT1,
    const float* __restrict__ bfold, float* __restrict__ G,
    const float* __restrict__ ls, const float* __restrict__ lb,
    float* __restrict__ bstate, f16* __restrict__ Ahb0, f16* __restrict__ Ahb1,
    const f16* __restrict__ WcT0, const f16* __restrict__ WcT1,
    const float* __restrict__ bp1, const float* __restrict__ Oproj,
    f16* __restrict__ hq0, f16* __restrict__ hq1,
    const f16* __restrict__ WlT0, const f16* __restrict__ WlT1,
    const float* __restrict__ bp2, const float* __restrict__ bo2,
    float* __restrict__ lg,
    const float* __restrict__ u_noise, float* __restrict__ out,
    const float* __restrict__ Wi1, const float* __restrict__ Aproj) {
    extern __shared__ char smem[];
    const int tid = threadIdx.x;
    unsigned gen = 0;

    for (int t = 0; t < T_STEPS; t++) {
        // ---- gates = [h1|b] @ Wbig + bfold  (256x3072, K=2048), 192 tiles ----
        gemm_phase<0>(Ahb0, Ahb1, 2048, WbT0, WbT1, 2048,
                      G, nullptr, nullptr, 3072, bfold, nullptr, nullptr, 48, smem);
        gbar(gen);

        // ---- LayerNorm + GRU (one row per CTA) ----
        {
            int row = blockIdx.x;
            if (row < BATCH) {
                float* sg = (float*)smem;          // 3072 floats
                float* red = sg + 3072;            // 128 floats
                const float* g = G + (size_t)row * 3072;
                for (int j = tid; j < 3072; j += 128) sg[j] = __ldcg(g + j);
                __syncthreads();
                float s = 0.0f;
                for (int j = tid; j < 3072; j += 128) s += sg[j];
                red[tid] = s; __syncthreads();
                for (int o = 64; o > 0; o >>= 1) {
                    if (tid < o) red[tid] += red[tid + o];
                    __syncthreads();
                }
                float mu = red[0] * (1.0f / 3072.0f);
                __syncthreads();
                s = 0.0f;
                for (int j = tid; j < 3072; j += 128) { float d = sg[j] - mu; s += d * d; }
                red[tid] = s; __syncthreads();
                for (int o = 64; o > 0; o >>= 1) {
                    if (tid < o) red[tid] += red[tid + o];
                    __syncthreads();
                }
                float inv = 1.0f / sqrtf(red[0] * (1.0f / 3072.0f) + 1e-3f);
                float* b = bstate + (size_t)row * 1024;
                for (int j = tid; j < 1024; j += 128) {
                    float r = (sg[j]        - mu) * inv * ls[j]        + lb[j];
                    float c = (sg[1024 + j] - mu) * inv * ls[1024 + j] + lb[1024 + j];
                    float u = (sg[2048 + j] - mu) * inv * ls[2048 + j] + lb[2048 + j];
                    float reset = sigm(r);
                    float cand  = tanhf(reset * c);
                    float upd   = sigm(u - 1.0f);
                    float bn2 = upd * cand + (1.0f - upd) * b[j];
                    b[j] = bn2;
                    size_t o = (size_t)row * 2048 + 1024 + j;
                    split2(bn2, Ahb0[o], Ahb1[o]);
                }
            }
        }
        gbar(gen);

        // ---- hq = silu(b @ [Wp1|Wo1_bot] + {bp1 | Oproj[t]})  (256x2048, K=1024) ----
        gemm_phase<3>(Ahb0 + 1024, Ahb1 + 1024, 2048, WcT0, WcT1, 1024,
                      nullptr, hq0, hq1, 2048, bp1, nullptr,
                      Oproj + (size_t)t * BATCH * 1024, 32, smem);
        gbar(gen);

        // ---- logits = [h_p @ Wp2 + bp2 | h_o @ Wo2 + bo2]  (256x2048, K=1024) ----
        gemm_phase<0>(hq0, hq1, 2048, WlT0, WlT1, 1024,
                      lg, nullptr, nullptr, 2048, bp2, bo2, nullptr, 32, smem);
        gbar(gen);

        // ---- head (softmax/KL/gumbel) + zgather for t+1 (one row per CTA) ----
        {
            int row = blockIdx.x;
            if (row < BATCH) {
                const int lane = tid & 31, w = tid >> 5;
                float* klp = (float*)smem;            // 32 floats
                int* idxs = (int*)(smem + 128);       // 32 ints
                const float* base = lg + (size_t)row * 2048;
                const float* un = u_noise + ((size_t)t * BATCH + row) * 1024;
                for (int sg2 = w; sg2 < 32; sg2 += 4) {
                    float pl = __ldcg(base + sg2 * 32 + lane);
                    pl = fminf(fmaxf(pl, -20.0f), 20.0f);
                    float mx = pl;
#pragma unroll
                    for (int o = 16; o > 0; o >>= 1) mx = fmaxf(mx, __shfl_xor_sync(0xffffffffu, mx, o));
                    float e = expf(pl - mx);
                    float sm = e;
#pragma unroll
                    for (int o = 16; o > 0; o >>= 1) sm += __shfl_xor_sync(0xffffffffu, sm, o);
                    float pp = e / sm * 0.99f + 0.0003125f;

                    float ql = __ldcg(base + 1024 + sg2 * 32 + lane);
                    ql = fminf(fmaxf(ql, -20.0f), 20.0f);
                    float mx2 = ql;
#pragma unroll
                    for (int o = 16; o > 0; o >>= 1) mx2 = fmaxf(mx2, __shfl_xor_sync(0xffffffffu, mx2, o));
                    float e2 = expf(ql - mx2);
                    float sm2 = e2;
#pragma unroll
                    for (int o = 16; o > 0; o >>= 1) sm2 += __shfl_xor_sync(0xffffffffu, sm2, o);
                    float qp = e2 / sm2 * 0.99f + 0.0003125f;

                    float kle = qp * (logf(qp + 1e-8f) - logf(pp + 1e-8f));
                    float kl = kle;
#pragma unroll
                    for (int o = 16; o > 0; o >>= 1) kl += __shfl_xor_sync(0xffffffffu, kl, o);

                    float u = un[sg2 * 32 + lane];
                    float gg = -logf(-logf(u + 1e-6f) + 1e-6f);
                    float val = logf(fmaxf(qp, 1e-6f)) + gg;
                    int idx = lane;
#pragma unroll
                    for (int o = 16; o > 0; o >>= 1) {
                        float ov = __shfl_down_sync(0xffffffffu, val, o);
                        int   oi = __shfl_down_sync(0xffffffffu, idx, o);
                        if (ov > val || (ov == val && oi < idx)) { val = ov; idx = oi; }
                    }
                    if (lane == 0) { klp[sg2] = kl; idxs[sg2] = sg2 * 32 + idx; }
                }
                __syncthreads();
                if (tid == 0) {
                    float kl = 0.0f;
                    for (int s2 = 0; s2 < 32; s2++) kl += klp[s2];
                    out[t * BATCH + row] = 1.1f * fmaxf(kl, 0.1f);
                }
                if (t + 1 < T_STEPS) {
                    const float* Ap2 = Aproj + ((size_t)(t + 1) * BATCH + row) * 1024;
                    for (int j = tid; j < 1024; j += 128) {
                        float acc = Ap2[j];
#pragma unroll
                        for (int s2 = 0; s2 < 32; s2++)
                            acc += Wi1[(size_t)idxs[s2] * 1024 + j];
                        float v = siluf(acc);
                        size_t o = (size_t)row * 2048 + j;
                        split2(v, Ahb0[o], Ahb1[o]);
                    }
                }
                __syncthreads();
            }
        }
        gbar(gen);
    }
}

// ============ standalone GEMM for prep (Oproj) ============
template <int MODE>
__global__ void __launch_bounds__(128) tgemm(
    const f16* __restrict__ A0c, const f16* __restrict__ A1c, int lda,
    const f16* __restrict__ W0c, const f16* __restrict__ W1c, int K,
    float* __restrict__ Cf, f16* __restrict__ C0, f16* __restrict__ C1, int ldc,
    const float* __restrict__ bias, const float* __restrict__ bias2,
    const float* __restrict__ aux, int nbx) {
    extern __shared__ char smem[];
    // single-tile path: map blockIdx.{x,y} onto the phase helper's tile loop
    const int tile = blockIdx.y * nbx + blockIdx.x;
    // reuse body with a 1-tile loop: emulate by temporary grid-strided call
    // (NCTA stride never triggers since tile < nbx*4 <= gridDim)
    {
        const uint32_t sb = smem_u32(smem);
        const int tid = threadIdx.x, wid = tid >> 5, lane = tid & 31;
        const int nk = K >> 6, NIT = 3 * nk;
        const int tA[3] = {0, 0, 1};
        const int tB[3] = {0, 1, 0};
        const int lr = tid >> 3, lc = tid & 7;
        const int wm = (wid >> 1) * 32, wn = (wid & 1) * 32;
        const int bn = (tile % nbx) * 64, bm = (tile / nbx) * 64;

        uint32_t aoff[2], boff[2];
#pragma unroll
        for (int mt = 0; mt < 2; mt++)
            aoff[mt] = (uint32_t)(wm + mt * 16 + (lane & 7) + ((lane >> 3) & 1) * 8) * 144
                     + ((lane >> 4) & 1) * 16;
#pragma unroll
        for (int np = 0; np < 2; np++)
            boff[np] = 9216 + (uint32_t)(wn + np * 16 + (lane & 7) + ((lane >> 4) & 1) * 8) * 144
                     + ((lane >> 3) & 1) * 16;

        const f16* Ap[2] = {A0c + (size_t)bm * lda, A1c + (size_t)bm * lda};
        const f16* Wp[2] = {W0c + (size_t)bn * K, W1c + (size_t)bn * K};

        float acc[2][4][4];
#pragma unroll
        for (int i = 0; i < 2; i++)
#pragma unroll
            for (int j = 0; j < 4; j++)
#pragma unroll
                for (int q = 0; q < 4; q++) acc[i][j][q] = 0.0f;

        auto issue = [&](int chunk) {
            int term = chunk / nk, kc = chunk - term * nk;
            const f16* As = Ap[tA[term]] + kc * 64;
            const f16* Ws = Wp[tB[term]] + kc * 64;
            uint32_t st = sb + (chunk & 3) * STG;
#pragma unroll
            for (int i = 0; i < 4; i++) {
                int row = lr + i * 16;
                cp16(st + row * 144 + lc * 16, As + (size_t)row * lda + lc * 8);
                cp16(st + 9216 + row * 144 + lc * 16, Ws + (size_t)row * K + lc * 8);
            }
        };
        issue(0); CP_COMMIT();
        issue(1); CP_COMMIT();
        issue(2); CP_COMMIT();
        for (int it = 0; it < NIT; it++) {
            CP_WAIT2();
            __syncthreads();
            uint32_t base = sb + (it & 3) * STG;
#pragma unroll
            for (int ks = 0; ks < 4; ks++) {
                uint32_t af[2][4], bfr[2][4];
#pragma unroll
                for (int mt = 0; mt < 2; mt++) ldsm4(af[mt], base + aoff[mt] + ks * 32);
#pragma unroll
                for (int np = 0; np < 2; np++) ldsm4(bfr[np], base + boff[np] + ks * 32);
#pragma unroll
                for (int mt = 0; mt < 2; mt++) {
#pragma unroll
                    for (int nt = 0; nt < 4; nt++)
                        mma16816(acc[mt][nt], af[mt], bfr[nt >> 1][(nt & 1) * 2],
                                 bfr[nt >> 1][(nt & 1) * 2 + 1]);
                }
            }
            if (it + 3 < NIT) issue(it + 3);
            CP_COMMIT();
        }
        const int er = lane >> 2, ec = (lane & 3) * 2;
#pragma unroll
        for (int mt = 0; mt < 2; mt++) {
#pragma unroll
            for (int nt = 0; nt < 4; nt++) {
                int m0 = bm + wm + mt * 16 + er;
                int n0 = bn + wn + nt * 8 + ec;
                float* a = acc[mt][nt];
                float b0 = bias[n0], b1 = bias[n0 + 1];
                float2 v0 = {a[0] + b0, a[1] + b1};
                float2 v1 = {a[2] + b0, a[3] + b1};
                *(float2*)(Cf + (size_t)m0 * ldc + n0) = v0;
                *(float2*)(Cf + (size_t)(m0 + 8) * ldc + n0) = v1;
            }
        }
    }
}

// ============ SIMT fp32 GEMM (prep + step0) ============
#define BM 64
#define BN 64
#define BKT 16
template <int MODE>
__global__ void gemm_k(const float* __restrict__ A, int lda,
                       const float* __restrict__ W, int ldw,
                       float* __restrict__ C, int ldc, int K,
                       const float* __restrict__ bias,
                       const float* __restrict__ aux, int auxld) {
    __shared__ float As[BKT][BM + 4];
    __shared__ float Bs[BKT][BN];
    const int bn = blockIdx.x * BN, bm = blockIdx.y * BM, tid = threadIdx.x;
    const int tx = tid & 15, ty = tid >> 4;
    const int arow = tid >> 2, avec = tid & 3;
    const int wrow = tid >> 4, wvec = tid & 15;
    float acc[4][4];
#pragma unroll
    for (int i = 0; i < 4; i++)
#pragma unroll
        for (int j = 0; j < 4; j++) acc[i][j] = 0.0f;
    for (int k0 = 0; k0 < K; k0 += BKT) {
        float4 a4 = *(const float4*)(A + (size_t)(bm + arow) * lda + k0 + avec * 4);
        As[avec * 4 + 0][arow] = a4.x;
        As[avec * 4 + 1][arow] = a4.y;
        As[avec * 4 + 2][arow] = a4.z;
        As[avec * 4 + 3][arow] = a4.w;
        *(float4*)&Bs[wrow][wvec * 4] =
            *(const float4*)(W + (size_t)(k0 + wrow) * ldw + bn + wvec * 4);
        __syncthreads();
#pragma unroll
        for (int k = 0; k < BKT; k++) {
            float4 ar = *(const float4*)&As[k][ty * 4];
            float4 br = *(const float4*)&Bs[k][tx * 4];
            acc[0][0] += ar.x * br.x; acc[0][1] += ar.x * br.y;
            acc[0][2] += ar.x * br.z; acc[0][3] += ar.x * br.w;
            acc[1][0] += ar.y * br.x; acc[1][1] += ar.y * br.y;
            acc[1][2] += ar.y * br.z; acc[1][3] += ar.y * br.w;
            acc[2][0] += ar.z * br.x; acc[2][1] += ar.z * br.y;
            acc[2][2] += ar.z * br.z; acc[2][3] += ar.z * br.w;
            acc[3][0] += ar.w * br.x; acc[3][1] += ar.w * br.y;
            acc[3][2] += ar.w * br.z; acc[3][3] += ar.w * br.w;
        }
        __syncthreads();
    }
#pragma unroll
    for (int i = 0; i < 4; i++) {
        int m = bm + ty * 4 + i;
#pragma unroll
        for (int j = 0; j < 4; j++) {
            int gn = bn + tx * 4 + j;
            float v = acc[i][j];
            if (MODE == 0) { if (bias) v += bias[gn]; }
            else           { v = siluf(v + aux[(size_t)m * auxld + gn]); }
            C[(size_t)m * ldc + gn] = v;
        }
    }
}

// ============ prep kernels ============
__global__ void k_aproj(const float* __restrict__ actions, const float* __restrict__ Wi1,
                        const float* __restrict__ bi1, float* __restrict__ out) {
    int idx = blockIdx.x * 256 + threadIdx.x;
    int r = idx >> 10, j = idx & 1023;
    const float* act = actions + (size_t)r * 6;
    float acc = bi1[j];
#pragma unroll
    for (int q = 0; q < 6; q++) acc += act[q] * Wi1[(size_t)(1024 + q) * 1024 + j];
    out[idx] = acc;
}
__global__ void k_split2(const float* __restrict__ src, f16* __restrict__ d0,
                         f16* __restrict__ d1) {
    size_t i = (size_t)blockIdx.x * 256 + threadIdx.x;
    split2(src[i], d0[i], d1[i]);
}
__global__ void k_splitT2(const float* __restrict__ src, int ldsrc,
                          f16* __restrict__ d0, f16* __restrict__ d1, int K) {
    size_t idx = (size_t)blockIdx.x * 256 + threadIdx.x;
    int n = (int)(idx / K), k = (int)(idx % K);
    split2(src[(size_t)k * ldsrc + n], d0[idx], d1[idx]);
}
__global__ void k_wcatT2(const float* __restrict__ Wp1, const float* __restrict__ Wo1,
                         f16* __restrict__ d0, f16* __restrict__ d1) {
    size_t idx = (size_t)blockIdx.x * 256 + threadIdx.x;
    int n = (int)(idx >> 10), k = (int)(idx & 1023);
    float v = (n < 1024) ? Wp1[(size_t)k * 1024 + n]
                         : Wo1[(size_t)(1024 + k) * 1024 + (n - 1024)];
    split2(v, d0[idx], d1[idx]);
}
__global__ void k_wlgT2(const float* __restrict__ Wp2, const float* __restrict__ Wo2,
                        f16* __restrict__ d0, f16* __restrict__ d1) {
    size_t idx = (size_t)blockIdx.x * 256 + threadIdx.x;
    int n = (int)(idx >> 10), k = (int)(idx & 1023);
    float v = (n < 1024) ? Wp2[(size_t)k * 1024 + n] : Wo2[(size_t)k * 1024 + (n - 1024)];
    split2(v, d0[idx], d1[idx]);
}
__global__ void k_bfold(const float* __restrict__ bi2, const float* __restrict__ Wg,
                        float* __restrict__ bf) {
    int n = blockIdx.x * 256 + threadIdx.x;
    if (n >= 3072) return;
    float acc = 0.0f;
    for (int k = 0; k < 1024; k++) acc += bi2[k] * Wg[(size_t)k * 3072 + n];
    bf[n] = acc;
}
__global__ void k_copy_wg_bot(const float* __restrict__ Wg, float* __restrict__ Wbig) {
    size_t idx = (size_t)blockIdx.x * 256 + threadIdx.x;
    Wbig[(size_t)1024 * 3072 + idx] = Wg[(size_t)1024 * 3072 + idx];
}
__global__ void k_initb(const float* __restrict__ b0, float* __restrict__ bstate,
                        f16* __restrict__ A0, f16* __restrict__ A1) {
    int idx = blockIdx.x * 256 + threadIdx.x;
    int m = idx >> 10, j = idx & 1023;
    float v = b0[idx];
    bstate[idx] = v;
    size_t o = (size_t)m * 2048 + 1024 + j;
    split2(v, A0[o], A1[o]);
}
__global__ void k_cvt_h1(const float* __restrict__ src, f16* __restrict__ A0,
                         f16* __restrict__ A1) {
    int idx = blockIdx.x * 256 + threadIdx.x;
    int m = idx >> 10, j = idx & 1023;
    size_t o = (size_t)m * 2048 + j;
    split2(src[idx], A0[o], A1[o]);
}

// ============ launch ============
extern "C" void kernel_launch(void* const* d_in, const int* in_sizes, int n_in,
                              void* d_out, int out_size) {
    const float* b0      = (const float*)d_in[0];
    const float* z0      = (const float*)d_in[1];
    const float* actions = (const float*)d_in[2];
    const float* obs     = (const float*)d_in[3];
    const float* u_noise = (const float*)d_in[4];
    const float* Wi1     = (const float*)d_in[5];
    const float* bi1     = (const float*)d_in[6];
    const float* Wi2     = (const float*)d_in[7];
    const float* bi2     = (const float*)d_in[8];
    const float* Wg      = (const float*)d_in[9];
    const float* ln_s    = (const float*)d_in[10];
    const float* ln_b    = (const float*)d_in[11];
    const float* Wo1     = (const float*)d_in[12];
    const float* bo1     = (const float*)d_in[13];
    const float* Wo2     = (const float*)d_in[14];
    const float* bo2     = (const float*)d_in[15];
    const float* Wp1     = (const float*)d_in[16];
    const float* bp1     = (const float*)d_in[17];
    const float* Wp2     = (const float*)d_in[18];
    const float* bp2     = (const float*)d_in[19];
    float* out = (float*)d_out;

    float *Aproj, *Oproj, *Wbig, *bfold, *G, *lgp, *tmp, *bstate;
    f16 *ob0, *ob1, *Wo1T0, *Wo1T1, *WbT0, *WbT1;
    f16 *WcT0, *WcT1, *WlT0, *WlT1, *Ahb0, *Ahb1, *hq0, *hq1;
    cudaGetSymbolAddress((void**)&Aproj, g_Aproj);
    cudaGetSymbolAddress((void**)&Oproj, g_Oproj);
    cudaGetSymbolAddress((void**)&Wbig, g_Wbig);
    cudaGetSymbolAddress((void**)&bfold, g_bfold);
    cudaGetSymbolAddress((void**)&G, g_G);
    cudaGetSymbolAddress((void**)&lgp, g_lg);
    cudaGetSymbolAddress((void**)&tmp, g_tmp);
    cudaGetSymbolAddress((void**)&bstate, g_bstate);
    cudaGetSymbolAddress((void**)&ob0, g_obs0);
    cudaGetSymbolAddress((void**)&ob1, g_obs1);
    cudaGetSymbolAddress((void**)&Wo1T0, g_Wo1T0);
    cudaGetSymbolAddress((void**)&Wo1T1, g_Wo1T1);
    cudaGetSymbolAddress((void**)&WbT0, g_WbT0);
    cudaGetSymbolAddress((void**)&WbT1, g_WbT1);
    cudaGetSymbolAddress((void**)&WcT0, g_WcT0);
    cudaGetSymbolAddress((void**)&WcT1, g_WcT1);
    cudaGetSymbolAddress((void**)&WlT0, g_WlT0);
    cudaGetSymbolAddress((void**)&WlT1, g_WlT1);
    cudaGetSymbolAddress((void**)&Ahb0, g_Ahb0);
    cudaGetSymbolAddress((void**)&Ahb1, g_Ahb1);
    cudaGetSymbolAddress((void**)&hq0, g_hq0);
    cudaGetSymbolAddress((void**)&hq1, g_hq1);

    cudaFuncSetAttribute(tgemm<0>, cudaFuncAttributeMaxDynamicSharedMemorySize, TG_DSMEM);
    cudaFuncSetAttribute(k_scan, cudaFuncAttributeMaxDynamicSharedMemorySize, TG_DSMEM);

    // ---- prep (time-parallel) ----
    k_aproj<<<T_STEPS * BATCH * 1024 / 256, 256>>>(actions, Wi1, bi1, Aproj);
    k_split2<<<T_STEPS * BATCH * 1024 / 256, 256>>>(obs, ob0, ob1);
    k_splitT2<<<1024 * 1024 / 256, 256>>>(Wo1, 1024, Wo1T0, Wo1T1, 1024);
    tgemm<0><<<dim3(16, 256), 128, TG_DSMEM>>>(ob0, ob1, 1024, Wo1T0, Wo1T1, 1024,
                                               Oproj, nullptr, nullptr, 1024,
                                               bo1, nullptr, nullptr, 16);
    gemm_k<0><<<dim3(3072 / BN, 1024 / BM), 256>>>(Wi2, 1024, Wg, 3072, Wbig, 3072, 1024,
                                                   nullptr, nullptr, 0);
    k_copy_wg_bot<<<1024 * 3072 / 256, 256>>>(Wg, Wbig);
    k_splitT2<<<3072 * 2048 / 256, 256>>>(Wbig, 3072, WbT0, WbT1, 2048);
    k_bfold<<<12, 256>>>(bi2, Wg, bfold);
    k_wcatT2<<<2048 * 1024 / 256, 256>>>(Wp1, Wo1, WcT0, WcT1);
    k_wlgT2<<<2048 * 1024 / 256, 256>>>(Wp2, Wo2, WlT0, WlT1);
    k_initb<<<BATCH * 1024 / 256, 256>>>(b0, bstate, Ahb0, Ahb1);
    // step-0 h1 (dense z0 GEMM)
    gemm_k<1><<<dim3(1024 / BN, BATCH / BM), 256>>>(z0, 1024, Wi1, 1024, tmp, 1024,
                                                    1024, nullptr, Aproj, 1024);
    k_cvt_h1<<<BATCH * 1024 / 256, 256>>>(tmp, Ahb0, Ahb1);

    // ---- persistent scan ----
    k_reset<<<1, 1>>>();
    k_scan<<<NCTA, 128, TG_DSMEM>>>(WbT0, WbT1, bfold, G, ln_s, ln_b, bstate,
                                    Ahb0, Ahb1, WcT0, WcT1, bp1, Oproj,
                                    hq0, hq1, WlT0, WlT1, bp2, bo2, lgp,
                                    u_noise, out, Wi1, Aproj);
}

// round 14
// speedup vs baseline: 1.2276x; 1.2276x over previous
#include <cuda_runtime.h>
#include <cuda_fp16.h>
#include <math.h>
#include <stdint.h>

#define T_STEPS 64
#define BATCH   256
typedef __half f16;

__device__ __forceinline__ uint32_t smem_u32(const void* p) {
    uint32_t a;
    asm("{ .reg .u64 t; cvta.to.shared.u64 t, %1; cvt.u32.u64 %0, t; }" : "=r"(a) : "l"(p));
    return a;
}
__device__ __forceinline__ void cp16(uint32_t dst, const void* src) {
    asm volatile("cp.async.cg.shared.global [%0], [%1], 16;" :: "r"(dst), "l"(src));
}
#define CP_COMMIT() asm volatile("cp.async.commit_group;" ::: "memory")
#define CP_WAIT2()  asm volatile("cp.async.wait_group 2;" ::: "memory")

__device__ __forceinline__ void ldsm4(uint32_t* r, uint32_t addr) {
    asm volatile("ldmatrix.sync.aligned.m8n8.x4.shared.b16 {%0,%1,%2,%3}, [%4];"
                 : "=r"(r[0]), "=r"(r[1]), "=r"(r[2]), "=r"(r[3]) : "r"(addr));
}
__device__ __forceinline__ void mma16816(float* c, const uint32_t* a, uint32_t b0, uint32_t b1) {
    asm volatile("mma.sync.aligned.m16n8k16.row.col.f32.f16.f16.f32 "
                 "{%0,%1,%2,%3}, {%4,%5,%6,%7}, {%8,%9}, {%0,%1,%2,%3};"
                 : "+f"(c[0]), "+f"(c[1]), "+f"(c[2]), "+f"(c[3])
                 : "r"(a[0]), "r"(a[1]), "r"(a[2]), "r"(a[3]), "r"(b0), "r"(b1));
}

// ============ scratch ============
__device__ float g_Aproj[T_STEPS * BATCH * 1024];
__device__ float g_Oproj[T_STEPS * BATCH * 1024];
__device__ float g_Wbig[2048 * 3072];
__device__ float g_bfold[3072];
__device__ float g_G[BATCH * 3072];
__device__ float g_lg[BATCH * 2048];
__device__ float g_tmp[BATCH * 1024];
__device__ float g_bstate[BATCH * 1024];
__device__ f16 g_obs0[T_STEPS * BATCH * 1024], g_obs1[T_STEPS * BATCH * 1024];
__device__ f16 g_Wo1T0[1024 * 1024], g_Wo1T1[1024 * 1024];
__device__ f16 g_WbT0[3072 * 2048], g_WbT1[3072 * 2048];
__device__ f16 g_WcT0[2048 * 1024], g_WcT1[2048 * 1024];
__device__ f16 g_WlT0[2048 * 1024], g_WlT1[2048 * 1024];
__device__ f16 g_Ahb0[BATCH * 2048], g_Ahb1[BATCH * 2048];
__device__ f16 g_hq0[BATCH * 2048], g_hq1[BATCH * 2048];

__device__ __forceinline__ float siluf(float x) { return x / (1.0f + expf(-x)); }
__device__ __forceinline__ float sigm(float x)  { return 1.0f / (1.0f + expf(-x)); }
__device__ __forceinline__ void split2(float v, f16& h, f16& l) {
    h = __float2half_rn(v);
    l = __float2half_rn(v - __half2float(h));
}

// ============ tg64: R7 GEMM verbatim (128 thr, tile 64x64) — prep Oproj ============
#define STG64 18432
#define DS64 (4 * STG64)

template <int MODE>
__global__ void __launch_bounds__(128) tg64(
    const f16* __restrict__ A0c, const f16* __restrict__ A1c, int lda,
    const f16* __restrict__ W0c, const f16* __restrict__ W1c, int K,
    float* __restrict__ Cf, f16* __restrict__ C0, f16* __restrict__ C1, int ldc,
    const float* __restrict__ bias, const float* __restrict__ bias2,
    const float* __restrict__ aux) {
    extern __shared__ char smem[];
    const uint32_t sb = smem_u32(smem);
    const int tid = threadIdx.x, wid = tid >> 5, lane = tid & 31;
    const int bn = blockIdx.x * 64, bm = blockIdx.y * 64;

    const f16* A0 = A0c; const f16* A1 = A1c;
    const float* biasp = bias;
    if (MODE == 0 && bias2 != nullptr && bn >= 1024) {
        A0 += 1024; A1 += 1024; biasp = bias2 - 1024;
    }
    const f16* Ap[2] = {A0 + (size_t)bm * lda, A1 + (size_t)bm * lda};
    const f16* Wp[2] = {W0c + (size_t)bn * K, W1c + (size_t)bn * K};

    const int nk = K >> 6;
    const int NIT = 3 * nk;
    const int tA[3] = {0, 0, 1};
    const int tB[3] = {0, 1, 0};

    const int lr = tid >> 3, lc = tid & 7;
    const int wm = (wid >> 1) * 32, wn = (wid & 1) * 32;

    uint32_t aoff[2], boff[2];
#pragma unroll
    for (int mt = 0; mt < 2; mt++)
        aoff[mt] = (uint32_t)(wm + mt * 16 + (lane & 7) + ((lane >> 3) & 1) * 8) * 144
                 + ((lane >> 4) & 1) * 16;
#pragma unroll
    for (int np = 0; np < 2; np++)
        boff[np] = 9216 + (uint32_t)(wn + np * 16 + (lane & 7) + ((lane >> 4) & 1) * 8) * 144
                 + ((lane >> 3) & 1) * 16;

    float acc[2][4][4];
#pragma unroll
    for (int i = 0; i < 2; i++)
#pragma unroll
        for (int j = 0; j < 4; j++)
#pragma unroll
            for (int q = 0; q < 4; q++) acc[i][j][q] = 0.0f;

    auto issue = [&](int chunk) {
        int term = chunk / nk, kc = chunk - term * nk;
        const f16* As = Ap[tA[term]] + kc * 64;
        const f16* Ws = Wp[tB[term]] + kc * 64;
        uint32_t st = sb + (chunk & 3) * STG64;
#pragma unroll
        for (int i = 0; i < 4; i++) {
            int row = lr + i * 16;
            cp16(st + row * 144 + lc * 16, As + (size_t)row * lda + lc * 8);
            cp16(st + 9216 + row * 144 + lc * 16, Ws + (size_t)row * K + lc * 8);
        }
    };

    issue(0); CP_COMMIT();
    issue(1); CP_COMMIT();
    issue(2); CP_COMMIT();

    for (int it = 0; it < NIT; it++) {
        CP_WAIT2();
        __syncthreads();
        uint32_t base = sb + (it & 3) * STG64;
#pragma unroll
        for (int ks = 0; ks < 4; ks++) {
            uint32_t af[2][4], bfr[2][4];
#pragma unroll
            for (int mt = 0; mt < 2; mt++) ldsm4(af[mt], base + aoff[mt] + ks * 32);
#pragma unroll
            for (int np = 0; np < 2; np++) ldsm4(bfr[np], base + boff[np] + ks * 32);
#pragma unroll
            for (int mt = 0; mt < 2; mt++) {
#pragma unroll
                for (int nt = 0; nt < 4; nt++)
                    mma16816(acc[mt][nt], af[mt], bfr[nt >> 1][(nt & 1) * 2],
                             bfr[nt >> 1][(nt & 1) * 2 + 1]);
            }
        }
        if (it + 3 < NIT) issue(it + 3);
        CP_COMMIT();
    }

    const int er = lane >> 2, ec = (lane & 3) * 2;
#pragma unroll
    for (int mt = 0; mt < 2; mt++) {
#pragma unroll
        for (int nt = 0; nt < 4; nt++) {
            int m0 = bm + wm + mt * 16 + er;
            int n0 = bn + wn + nt * 8 + ec;
            float* a = acc[mt][nt];
            float b0 = biasp[n0], b1 = biasp[n0 + 1];
            float2 v0 = {a[0] + b0, a[1] + b1};
            float2 v1 = {a[2] + b0, a[3] + b1};
            *(float2*)(Cf + (size_t)m0 * ldc + n0) = v0;
            *(float2*)(Cf + (size_t)(m0 + 8) * ldc + n0) = v1;
        }
    }
}

// ============ tg32: same math, tile 64x32, 64 thr (2 warps in M) ============
// Bit-identical per-element K-chain to tg64/R7: term-major (hh,hl,lh),
// k-chunks ascending, ks 0..3, single accumulator.
#define PL32  9216
#define STG32 13824
#define DS32 (4 * STG32)

template <int MODE>
__global__ void __launch_bounds__(64, 4) tg32(
    const f16* __restrict__ A0c, const f16* __restrict__ A1c, int lda,
    const f16* __restrict__ W0c, const f16* __restrict__ W1c, int K,
    float* __restrict__ Cf, f16* __restrict__ C0, f16* __restrict__ C1, int ldc,
    const float* __restrict__ bias, const float* __restrict__ bias2,
    const float* __restrict__ aux) {
    extern __shared__ char smem[];
    const uint32_t sb = smem_u32(smem);
    const int tid = threadIdx.x, wid = tid >> 5, lane = tid & 31;
    const int bn = blockIdx.x * 32, bm = blockIdx.y * 64;

    const f16* A0 = A0c; const f16* A1 = A1c;
    const float* biasp = bias;
    if (MODE == 0 && bias2 != nullptr && bn >= 1024) {
        A0 += 1024; A1 += 1024; biasp = bias2 - 1024;
    }
    const f16* Ap[2] = {A0 + (size_t)bm * lda, A1 + (size_t)bm * lda};
    const f16* Wp[2] = {W0c + (size_t)bn * K, W1c + (size_t)bn * K};

    const int nk = K >> 6;
    const int NIT = 3 * nk;
    const int tA[3] = {0, 0, 1};
    const int tB[3] = {0, 1, 0};

    const int lr = tid >> 3, lc = tid & 7;
    const int wm = wid * 32;

    uint32_t aoff[2], boff[2];
#pragma unroll
    for (int mt = 0; mt < 2; mt++)
        aoff[mt] = (uint32_t)(wm + mt * 16 + (lane & 7) + ((lane >> 3) & 1) * 8) * 144
                 + ((lane >> 4) & 1) * 16;
#pragma unroll
    for (int np = 0; np < 2; np++)
        boff[np] = PL32 + (uint32_t)(np * 16 + (lane & 7) + ((lane >> 4) & 1) * 8) * 144
                 + ((lane >> 3) & 1) * 16;

    float acc[2][4][4];
#pragma unroll
    for (int i = 0; i < 2; i++)
#pragma unroll
        for (int j = 0; j < 4; j++)
#pragma unroll
            for (int q = 0; q < 4; q++) acc[i][j][q] = 0.0f;

    auto issue = [&](int chunk) {
        int term = chunk / nk, kc = chunk - term * nk;
        const f16* As = Ap[tA[term]] + kc * 64;
        const f16* Ws = Wp[tB[term]] + kc * 64;
        uint32_t st = sb + (chunk & 3) * STG32;
#pragma unroll
        for (int i = 0; i < 8; i++) {
            int row = lr + i * 8;
            cp16(st + row * 144 + lc * 16, As + (size_t)row * lda + lc * 8);
        }
#pragma unroll
        for (int i = 0; i < 4; i++) {
            int row = lr + i * 8;
            cp16(st + PL32 + row * 144 + lc * 16, Ws + (size_t)row * K + lc * 8);
        }
    };

    issue(0); CP_COMMIT();
    issue(1); CP_COMMIT();
    issue(2); CP_COMMIT();

    for (int it = 0; it < NIT; it++) {
        CP_WAIT2();
        __syncthreads();
        uint32_t base = sb + (it & 3) * STG32;
#pragma unroll
        for (int ks = 0; ks < 4; ks++) {
            uint32_t af[2][4], bfr[2][4];
#pragma unroll
            for (int mt = 0; mt < 2; mt++) ldsm4(af[mt], base + aoff[mt] + ks * 32);
#pragma unroll
            for (int np = 0; np < 2; np++) ldsm4(bfr[np], base + boff[np] + ks * 32);
#pragma unroll
            for (int mt = 0; mt < 2; mt++) {
#pragma unroll
                for (int nt = 0; nt < 4; nt++)
                    mma16816(acc[mt][nt], af[mt], bfr[nt >> 1][(nt & 1) * 2],
                             bfr[nt >> 1][(nt & 1) * 2 + 1]);
            }
        }
        if (it + 3 < NIT) issue(it + 3);
        CP_COMMIT();
    }

    const int er = lane >> 2, ec = (lane & 3) * 2;
#pragma unroll
    for (int mt = 0; mt < 2; mt++) {
#pragma unroll
        for (int nt = 0; nt < 4; nt++) {
            int m0 = bm + wm + mt * 16 + er;
            int n0 = bn + nt * 8 + ec;
            float* a = acc[mt][nt];
            if (MODE == 0) {
                float b0 = biasp[n0], b1 = biasp[n0 + 1];
                float2 v0 = {a[0] + b0, a[1] + b1};
                float2 v1 = {a[2] + b0, a[3] + b1};
                *(float2*)(Cf + (size_t)m0 * ldc + n0) = v0;
                *(float2*)(Cf + (size_t)(m0 + 8) * ldc + n0) = v1;
            } else {
                const bool left = (bn < 1024);
#pragma unroll
                for (int rr = 0; rr < 2; rr++) {
                    int m = m0 + rr * 8;
                    float ad0 = left ? bias[n0]     : aux[(size_t)m * 1024 + n0 - 1024];
                    float ad1 = left ? bias[n0 + 1] : aux[(size_t)m * 1024 + n0 + 1 - 1024];
                    float v0 = siluf(a[rr * 2 + 0] + ad0);
                    float v1 = siluf(a[rr * 2 + 1] + ad1);
                    f16 h0, l0, h1, l1;
                    split2(v0, h0, l0);
                    split2(v1, h1, l1);
                    *(__half2*)(C0 + (size_t)m * ldc + n0) = __halves2half2(h0, h1);
                    *(__half2*)(C1 + (size_t)m * ldc + n0) = __halves2half2(l0, l1);
                }
            }
        }
    }
}

// ============ SIMT fp32 GEMM (prep + step0) ============
#define BM 64
#define BN 64
#define BKT 16
template <int MODE>
__global__ void gemm_k(const float* __restrict__ A, int lda,
                       const float* __restrict__ W, int ldw,
                       float* __restrict__ C, int ldc, int K,
                       const float* __restrict__ bias,
                       const float* __restrict__ aux, int auxld) {
    __shared__ float As[BKT][BM + 4];
    __shared__ float Bs[BKT][BN];
    const int bn = blockIdx.x * BN, bm = blockIdx.y * BM, tid = threadIdx.x;
    const int tx = tid & 15, ty = tid >> 4;
    const int arow = tid >> 2, avec = tid & 3;
    const int wrow = tid >> 4, wvec = tid & 15;
    float acc[4][4];
#pragma unroll
    for (int i = 0; i < 4; i++)
#pragma unroll
        for (int j = 0; j < 4; j++) acc[i][j] = 0.0f;
    for (int k0 = 0; k0 < K; k0 += BKT) {
        float4 a4 = *(const float4*)(A + (size_t)(bm + arow) * lda + k0 + avec * 4);
        As[avec * 4 + 0][arow] = a4.x;
        As[avec * 4 + 1][arow] = a4.y;
        As[avec * 4 + 2][arow] = a4.z;
        As[avec * 4 + 3][arow] = a4.w;
        *(float4*)&Bs[wrow][wvec * 4] =
            *(const float4*)(W + (size_t)(k0 + wrow) * ldw + bn + wvec * 4);
        __syncthreads();
#pragma unroll
        for (int k = 0; k < BKT; k++) {
            float4 ar = *(const float4*)&As[k][ty * 4];
            float4 br = *(const float4*)&Bs[k][tx * 4];
            acc[0][0] += ar.x * br.x; acc[0][1] += ar.x * br.y;
            acc[0][2] += ar.x * br.z; acc[0][3] += ar.x * br.w;
            acc[1][0] += ar.y * br.x; acc[1][1] += ar.y * br.y;
            acc[1][2] += ar.y * br.z; acc[1][3] += ar.y * br.w;
            acc[2][0] += ar.z * br.x; acc[2][1] += ar.z * br.y;
            acc[2][2] += ar.z * br.z; acc[2][3] += ar.z * br.w;
            acc[3][0] += ar.w * br.x; acc[3][1] += ar.w * br.y;
            acc[3][2] += ar.w * br.z; acc[3][3] += ar.w * br.w;
        }
        __syncthreads();
    }
#pragma unroll
    for (int i = 0; i < 4; i++) {
        int m = bm + ty * 4 + i;
#pragma unroll
        for (int j = 0; j < 4; j++) {
            int gn = bn + tx * 4 + j;
            float v = acc[i][j];
            if (MODE == 0) { if (bias) v += bias[gn]; }
            else           { v = siluf(v + aux[(size_t)m * auxld + gn]); }
            C[(size_t)m * ldc + gn] = v;
        }
    }
}

// ============ prep / elementwise ============
__global__ void k_aproj(const float* __restrict__ actions, const float* __restrict__ Wi1,
                        const float* __restrict__ bi1, float* __restrict__ out) {
    int idx = blockIdx.x * 256 + threadIdx.x;
    int r = idx >> 10, j = idx & 1023;
    const float* act = actions + (size_t)r * 6;
    float acc = bi1[j];
#pragma unroll
    for (int q = 0; q < 6; q++) acc += act[q] * Wi1[(size_t)(1024 + q) * 1024 + j];
    out[idx] = acc;
}
__global__ void k_split2(const float* __restrict__ src, f16* __restrict__ d0,
                         f16* __restrict__ d1) {
    size_t i = (size_t)blockIdx.x * 256 + threadIdx.x;
    split2(src[i], d0[i], d1[i]);
}
// tiled transpose + split: dst[n][k] = src[k][n]
__global__ void k_tsplit(const float* __restrict__ src, int srcRows, int srcCols,
                         f16* __restrict__ d0, f16* __restrict__ d1) {
    __shared__ float tile[32][33];
    int n0 = blockIdx.x * 32, k0 = blockIdx.y * 32;
    int tx = threadIdx.x, ty = threadIdx.y;
#pragma unroll
    for (int i = 0; i < 4; i++) {
        int k = k0 + ty + i * 8;
        tile[ty + i * 8][tx] = src[(size_t)k * srcCols + n0 + tx];
    }
    __syncthreads();
#pragma unroll
    for (int i = 0; i < 4; i++) {
        int n = n0 + ty + i * 8;
        float v = tile[tx][ty + i * 8];
        size_t o = (size_t)n * srcRows + k0 + tx;
        split2(v, d0[o], d1[o]);
    }
}
__global__ void k_bfold(const float* __restrict__ bi2, const float* __restrict__ Wg,
                        float* __restrict__ bf) {
    int n = blockIdx.x * 256 + threadIdx.x;
    if (n >= 3072) return;
    float acc = 0.0f;
    for (int k = 0; k < 1024; k++) acc += bi2[k] * Wg[(size_t)k * 3072 + n];
    bf[n] = acc;
}
__global__ void k_copy_wg_bot(const float* __restrict__ Wg, float* __restrict__ Wbig) {
    size_t idx = (size_t)blockIdx.x * 256 + threadIdx.x;
    Wbig[(size_t)1024 * 3072 + idx] = Wg[(size_t)1024 * 3072 + idx];
}
__global__ void k_initb(const float* __restrict__ b0, float* __restrict__ bstate,
                        f16* __restrict__ A0, f16* __restrict__ A1) {
    int idx = blockIdx.x * 256 + threadIdx.x;
    int m = idx >> 10, j = idx & 1023;
    float v = b0[idx];
    bstate[idx] = v;
    size_t o = (size_t)m * 2048 + 1024 + j;
    split2(v, A0[o], A1[o]);
}
__global__ void k_cvt_h1(const float* __restrict__ src, f16* __restrict__ A0,
                         f16* __restrict__ A1) {
    int idx = blockIdx.x * 256 + threadIdx.x;
    int m = idx >> 10, j = idx & 1023;
    size_t o = (size_t)m * 2048 + j;
    split2(src[idx], A0[o], A1[o]);
}
__global__ void k_ln_gru(const float* __restrict__ G, const float* __restrict__ ls,
                         const float* __restrict__ lb, float* __restrict__ bstate,
                         f16* __restrict__ A0, f16* __restrict__ A1) {
    int row = blockIdx.x, tid = threadIdx.x;
    const float* g = G + (size_t)row * 3072;
    __shared__ float red[256];
    __shared__ float mu_s, inv_s;
    float s = 0.0f;
    for (int j = tid; j < 3072; j += 256) s += g[j];
    red[tid] = s; __syncthreads();
    for (int o = 128; o > 0; o >>= 1) { if (tid < o) red[tid] += red[tid + o]; __syncthreads(); }
    if (tid == 0) mu_s = red[0] * (1.0f / 3072.0f);
    __syncthreads();
    float mu = mu_s;
    s = 0.0f;
    for (int j = tid; j < 3072; j += 256) { float d = g[j] - mu; s += d * d; }
    red[tid] = s; __syncthreads();
    for (int o = 128; o > 0; o >>= 1) { if (tid < o) red[tid] += red[tid + o]; __syncthreads(); }
    if (tid == 0) inv_s = 1.0f / sqrtf(red[0] * (1.0f / 3072.0f) + 1e-3f);
    __syncthreads();
    float inv = inv_s;
    float* b = bstate + (size_t)row * 1024;
    for (int j = tid; j < 1024; j += 256) {
        float r = (g[j]        - mu) * inv * ls[j]        + lb[j];
        float c = (g[1024 + j] - mu) * inv * ls[1024 + j] + lb[1024 + j];
        float u = (g[2048 + j] - mu) * inv * ls[2048 + j] + lb[2048 + j];
        float reset = sigm(r);
        float cand  = tanhf(reset * c);
        float upd   = sigm(u - 1.0f);
        float bn2 = upd * cand + (1.0f - upd) * b[j];
        b[j] = bn2;
        size_t o = (size_t)row * 2048 + 1024 + j;
        split2(bn2, A0[o], A1[o]);
    }
}
__device__ __forceinline__ float wmax(float v) {
#pragma unroll
    for (int o = 16; o > 0; o >>= 1) v = fmaxf(v, __shfl_xor_sync(0xffffffffu, v, o));
    return v;
}
__device__ __forceinline__ float wsum(float v) {
#pragma unroll
    for (int o = 16; o > 0; o >>= 1) v += __shfl_xor_sync(0xffffffffu, v, o);
    return v;
}
// fused head (softmax/KL/gumbel) + zgather for next step (idxs via smem)
__global__ void k_head_z(const float* __restrict__ lg, const float* __restrict__ un,
                         float* __restrict__ out,
                         const float* __restrict__ Wi1, const float* __restrict__ Aproj_n,
                         int do_z, f16* __restrict__ A0, f16* __restrict__ A1) {
    int row = blockIdx.x, tid = threadIdx.x;
    int lane = tid & 31, w = tid >> 5;
    __shared__ float klp[32];
    __shared__ int idxs[32];
    const float* base = lg + (size_t)row * 2048;
    for (int sg = w; sg < 32; sg += 8) {
        float pl = base[sg * 32 + lane];
        pl = fminf(fmaxf(pl, -20.0f), 20.0f);
        float e = expf(pl - wmax(pl));
        float pp = e / wsum(e) * 0.99f + 0.0003125f;
        float ql = base[1024 + sg * 32 + lane];
        ql = fminf(fmaxf(ql, -20.0f), 20.0f);
        float e2 = expf(ql - wmax(ql));
        float qp = e2 / wsum(e2) * 0.99f + 0.0003125f;
        float kl = wsum(qp * (logf(qp + 1e-8f) - logf(pp + 1e-8f)));
        float u = un[(size_t)(row * 32 + sg) * 32 + lane];
        float gg = -logf(-logf(u + 1e-6f) + 1e-6f);
        float val = logf(fmaxf(qp, 1e-6f)) + gg;
        int idx = lane;
#pragma unroll
        for (int o = 16; o > 0; o >>= 1) {
            float ov = __shfl_down_sync(0xffffffffu, val, o);
            int   oi = __shfl_down_sync(0xffffffffu, idx, o);
            if (ov > val || (ov == val && oi < idx)) { val = ov; idx = oi; }
        }
        if (lane == 0) { klp[sg] = kl; idxs[sg] = sg * 32 + idx; }
    }
    __syncthreads();
    if (tid == 0) {
        float kl = 0.0f;
        for (int s = 0; s < 32; s++) kl += klp[s];
        out[row] = 1.1f * fmaxf(kl, 0.1f);
    }
    if (do_z) {
        for (int j = tid; j < 1024; j += 256) {
            float acc = Aproj_n[(size_t)row * 1024 + j];
#pragma unroll
            for (int s = 0; s < 32; s++) acc += Wi1[(size_t)idxs[s] * 1024 + j];
            float v = siluf(acc);
            size_t o = (size_t)row * 2048 + j;
            split2(v, A0[o], A1[o]);
        }
    }
}

// ============ launch ============
extern "C" void kernel_launch(void* const* d_in, const int* in_sizes, int n_in,
                              void* d_out, int out_size) {
    const float* b0      = (const float*)d_in[0];
    const float* z0      = (const float*)d_in[1];
    const float* actions = (const float*)d_in[2];
    const float* obs     = (const float*)d_in[3];
    const float* u_noise = (const float*)d_in[4];
    const float* Wi1     = (const float*)d_in[5];
    const float* bi1     = (const float*)d_in[6];
    const float* Wi2     = (const float*)d_in[7];
    const float* bi2     = (const float*)d_in[8];
    const float* Wg      = (const float*)d_in[9];
    const float* ln_s    = (const float*)d_in[10];
    const float* ln_b    = (const float*)d_in[11];
    const float* Wo1     = (const float*)d_in[12];
    const float* bo1     = (const float*)d_in[13];
    const float* Wo2     = (const float*)d_in[14];
    const float* bo2     = (const float*)d_in[15];
    const float* Wp1     = (const float*)d_in[16];
    const float* bp1     = (const float*)d_in[17];
    const float* Wp2     = (const float*)d_in[18];
    const float* bp2     = (const float*)d_in[19];
    float* out = (float*)d_out;

    float *Aproj, *Oproj, *Wbig, *bfold, *G, *lgp, *tmp, *bstate;
    f16 *ob0, *ob1, *Wo1T0, *Wo1T1, *WbT0, *WbT1;
    f16 *WcT0, *WcT1, *WlT0, *WlT1, *Ahb0, *Ahb1, *hq0, *hq1;
    cudaGetSymbolAddress((void**)&Aproj, g_Aproj);
    cudaGetSymbolAddress((void**)&Oproj, g_Oproj);
    cudaGetSymbolAddress((void**)&Wbig, g_Wbig);
    cudaGetSymbolAddress((void**)&bfold, g_bfold);
    cudaGetSymbolAddress((void**)&G, g_G);
    cudaGetSymbolAddress((void**)&lgp, g_lg);
    cudaGetSymbolAddress((void**)&tmp, g_tmp);
    cudaGetSymbolAddress((void**)&bstate, g_bstate);
    cudaGetSymbolAddress((void**)&ob0, g_obs0);
    cudaGetSymbolAddress((void**)&ob1, g_obs1);
    cudaGetSymbolAddress((void**)&Wo1T0, g_Wo1T0);
    cudaGetSymbolAddress((void**)&Wo1T1, g_Wo1T1);
    cudaGetSymbolAddress((void**)&WbT0, g_WbT0);
    cudaGetSymbolAddress((void**)&WbT1, g_WbT1);
    cudaGetSymbolAddress((void**)&WcT0, g_WcT0);
    cudaGetSymbolAddress((void**)&WcT1, g_WcT1);
    cudaGetSymbolAddress((void**)&WlT0, g_WlT0);
    cudaGetSymbolAddress((void**)&WlT1, g_WlT1);
    cudaGetSymbolAddress((void**)&Ahb0, g_Ahb0);
    cudaGetSymbolAddress((void**)&Ahb1, g_Ahb1);
    cudaGetSymbolAddress((void**)&hq0, g_hq0);
    cudaGetSymbolAddress((void**)&hq1, g_hq1);

    cudaFuncSetAttribute(tg64<0>, cudaFuncAttributeMaxDynamicSharedMemorySize, DS64);
    cudaFuncSetAttribute(tg32<0>, cudaFuncAttributeMaxDynamicSharedMemorySize, DS32);
    cudaFuncSetAttribute(tg32<3>, cudaFuncAttributeMaxDynamicSharedMemorySize, DS32);

    // ---- prep (time-parallel) ----
    k_aproj<<<T_STEPS * BATCH * 1024 / 256, 256>>>(actions, Wi1, bi1, Aproj);
    k_split2<<<T_STEPS * BATCH * 1024 / 256, 256>>>(obs, ob0, ob1);
    k_tsplit<<<dim3(32, 32), dim3(32, 8)>>>(Wo1, 1024, 1024, Wo1T0, Wo1T1);
    tg64<0><<<dim3(16, 256), 128, DS64>>>(ob0, ob1, 1024, Wo1T0, Wo1T1, 1024,
                                          Oproj, nullptr, nullptr, 1024,
                                          bo1, nullptr, nullptr);
    gemm_k<0><<<dim3(3072 / BN, 1024 / BM), 256>>>(Wi2, 1024, Wg, 3072, Wbig, 3072, 1024,
                                                   nullptr, nullptr, 0);
    k_copy_wg_bot<<<1024 * 3072 / 256, 256>>>(Wg, Wbig);
    k_tsplit<<<dim3(96, 64), dim3(32, 8)>>>(Wbig, 2048, 3072, WbT0, WbT1);
    k_bfold<<<12, 256>>>(bi2, Wg, bfold);
    k_tsplit<<<dim3(32, 32), dim3(32, 8)>>>(Wp1, 1024, 1024, WcT0, WcT1);
    k_tsplit<<<dim3(32, 32), dim3(32, 8)>>>(Wo1 + (size_t)1024 * 1024, 1024, 1024,
                                            WcT0 + (size_t)1024 * 1024,
                                            WcT1 + (size_t)1024 * 1024);
    k_tsplit<<<dim3(32, 32), dim3(32, 8)>>>(Wp2, 1024, 1024, WlT0, WlT1);
    k_tsplit<<<dim3(32, 32), dim3(32, 8)>>>(Wo2, 1024, 1024,
                                            WlT0 + (size_t)1024 * 1024,
                                            WlT1 + (size_t)1024 * 1024);
    k_initb<<<BATCH * 1024 / 256, 256>>>(b0, bstate, Ahb0, Ahb1);
    // step-0 h1 (dense z0 GEMM)
    gemm_k<1><<<dim3(1024 / BN, BATCH / BM), 256>>>(z0, 1024, Wi1, 1024, tmp, 1024,
                                                    1024, nullptr, Aproj, 1024);
    k_cvt_h1<<<BATCH * 1024 / 256, 256>>>(tmp, Ahb0, Ahb1);

    // ---- sequential scan ----
    for (int t = 0; t < T_STEPS; t++) {
        // gates = [h1|b] @ Wbig + bfold   (256 x 3072, K=2048) — 384 CTAs
        tg32<0><<<dim3(96, 4), 64, DS32>>>(Ahb0, Ahb1, 2048, WbT0, WbT1, 2048,
                                           G, nullptr, nullptr, 3072,
                                           bfold, nullptr, nullptr);
        k_ln_gru<<<BATCH, 256>>>(G, ln_s, ln_b, bstate, Ahb0, Ahb1);
        // hq = silu(b_new @ [Wp1|Wo1_bot] + {bp1 | Oproj[t]})  (256 x 2048, K=1024)
        tg32<3><<<dim3(64, 4), 64, DS32>>>(Ahb0 + 1024, Ahb1 + 1024, 2048,
                                           WcT0, WcT1, 1024,
                                           nullptr, hq0, hq1, 2048,
                                           bp1, nullptr, Oproj + (size_t)t * BATCH * 1024);
        // logits = [h_p @ Wp2 + bp2 | h_o @ Wo2 + bo2]  (256 x 2048, K=1024)
        tg32<0><<<dim3(64, 4), 64, DS32>>>(hq0, hq1, 2048, WlT0, WlT1, 1024,
                                           lgp, nullptr, nullptr, 2048,
                                           bp2, bo2, nullptr);
        // head + zgather(t+1)
        int do_z = (t + 1 < T_STEPS) ? 1 : 0;
        const float* apn = Aproj + (size_t)(do_z ? t + 1 : t) * BATCH * 1024;
        k_head_z<<<BATCH, 256>>>(lgp, u_noise + (size_t)t * BATCH * 1024,
                                 out + t * BATCH, Wi1, apn, do_z, Ahb0, Ahb1);
    }
}

// round 15
// speedup vs baseline: 1.2535x; 1.0210x over previous
#include <cuda_runtime.h>
#include <cuda_fp16.h>
#include <math.h>
#include <stdint.h>

#define T_STEPS 64
#define BATCH   256
typedef __half f16;

__device__ __forceinline__ uint32_t smem_u32(const void* p) {
    uint32_t a;
    asm("{ .reg .u64 t; cvta.to.shared.u64 t, %1; cvt.u32.u64 %0, t; }" : "=r"(a) : "l"(p));
    return a;
}
__device__ __forceinline__ void cp16(uint32_t dst, const void* src) {
    asm volatile("cp.async.cg.shared.global [%0], [%1], 16;" :: "r"(dst), "l"(src));
}
#define CP_COMMIT() asm volatile("cp.async.commit_group;" ::: "memory")
#define CP_WAIT2()  asm volatile("cp.async.wait_group 2;" ::: "memory")

__device__ __forceinline__ void ldsm4(uint32_t* r, uint32_t addr) {
    asm volatile("ldmatrix.sync.aligned.m8n8.x4.shared.b16 {%0,%1,%2,%3}, [%4];"
                 : "=r"(r[0]), "=r"(r[1]), "=r"(r[2]), "=r"(r[3]) : "r"(addr));
}
__device__ __forceinline__ void mma16816(float* c, const uint32_t* a, uint32_t b0, uint32_t b1) {
    asm volatile("mma.sync.aligned.m16n8k16.row.col.f32.f16.f16.f32 "
                 "{%0,%1,%2,%3}, {%4,%5,%6,%7}, {%8,%9}, {%0,%1,%2,%3};"
                 : "+f"(c[0]), "+f"(c[1]), "+f"(c[2]), "+f"(c[3])
                 : "r"(a[0]), "r"(a[1]), "r"(a[2]), "r"(a[3]), "r"(b0), "r"(b1));
}

// ============ scratch ============
__device__ float g_Aproj[T_STEPS * BATCH * 1024];
__device__ float g_Oproj[T_STEPS * BATCH * 1024];
__device__ float g_Wbig[2048 * 3072];
__device__ float g_bfold[3072];
__device__ float g_G[BATCH * 3072];
__device__ float g_lg[BATCH * 2048];
__device__ float g_tmp[BATCH * 1024];
__device__ float g_bstate[BATCH * 1024];
__device__ f16 g_obs0[T_STEPS * BATCH * 1024], g_obs1[T_STEPS * BATCH * 1024];
__device__ f16 g_Wo1T0[1024 * 1024], g_Wo1T1[1024 * 1024];
__device__ f16 g_WbT0[3072 * 2048], g_WbT1[3072 * 2048];
__device__ f16 g_WcT0[2048 * 1024], g_WcT1[2048 * 1024];
__device__ f16 g_WlT0[2048 * 1024], g_WlT1[2048 * 1024];
__device__ f16 g_Ahb0[BATCH * 2048], g_Ahb1[BATCH * 2048];
__device__ f16 g_hq0[BATCH * 2048], g_hq1[BATCH * 2048];

__device__ __forceinline__ float siluf(float x) { return x / (1.0f + expf(-x)); }
__device__ __forceinline__ float sigm(float x)  { return 1.0f / (1.0f + expf(-x)); }
__device__ __forceinline__ void split2(float v, f16& h, f16& l) {
    h = __float2half_rn(v);
    l = __float2half_rn(v - __half2float(h));
}

// ============ tg64: 128 thr, tile 64x64 — prep Oproj ============
#define STG64 18432
#define DS64 (4 * STG64)

template <int MODE>
__global__ void __launch_bounds__(128) tg64(
    const f16* __restrict__ A0c, const f16* __restrict__ A1c, int lda,
    const f16* __restrict__ W0c, const f16* __restrict__ W1c, int K,
    float* __restrict__ Cf, f16* __restrict__ C0, f16* __restrict__ C1, int ldc,
    const float* __restrict__ bias, const float* __restrict__ bias2,
    const float* __restrict__ aux) {
    extern __shared__ char smem[];
    const uint32_t sb = smem_u32(smem);
    const int tid = threadIdx.x, wid = tid >> 5, lane = tid & 31;
    const int bn = blockIdx.x * 64, bm = blockIdx.y * 64;

    const f16* A0 = A0c; const f16* A1 = A1c;
    const float* biasp = bias;
    if (MODE == 0 && bias2 != nullptr && bn >= 1024) {
        A0 += 1024; A1 += 1024; biasp = bias2 - 1024;
    }
    const f16* Ap[2] = {A0 + (size_t)bm * lda, A1 + (size_t)bm * lda};
    const f16* Wp[2] = {W0c + (size_t)bn * K, W1c + (size_t)bn * K};

    const int nk = K >> 6;
    const int NIT = 3 * nk;
    const int tA[3] = {0, 0, 1};
    const int tB[3] = {0, 1, 0};

    const int lr = tid >> 3, lc = tid & 7;
    const int wm = (wid >> 1) * 32, wn = (wid & 1) * 32;

    uint32_t aoff[2], boff[2];
#pragma unroll
    for (int mt = 0; mt < 2; mt++)
        aoff[mt] = (uint32_t)(wm + mt * 16 + (lane & 7) + ((lane >> 3) & 1) * 8) * 144
                 + ((lane >> 4) & 1) * 16;
#pragma unroll
    for (int np = 0; np < 2; np++)
        boff[np] = 9216 + (uint32_t)(wn + np * 16 + (lane & 7) + ((lane >> 4) & 1) * 8) * 144
                 + ((lane >> 3) & 1) * 16;

    float acc[2][4][4];
#pragma unroll
    for (int i = 0; i < 2; i++)
#pragma unroll
        for (int j = 0; j < 4; j++)
#pragma unroll
            for (int q = 0; q < 4; q++) acc[i][j][q] = 0.0f;

    auto issue = [&](int chunk) {
        int term = chunk / nk, kc = chunk - term * nk;
        const f16* As = Ap[tA[term]] + kc * 64;
        const f16* Ws = Wp[tB[term]] + kc * 64;
        uint32_t st = sb + (chunk & 3) * STG64;
#pragma unroll
        for (int i = 0; i < 4; i++) {
            int row = lr + i * 16;
            cp16(st + row * 144 + lc * 16, As + (size_t)row * lda + lc * 8);
            cp16(st + 9216 + row * 144 + lc * 16, Ws + (size_t)row * K + lc * 8);
        }
    };

    issue(0); CP_COMMIT();
    issue(1); CP_COMMIT();
    issue(2); CP_COMMIT();

    for (int it = 0; it < NIT; it++) {
        CP_WAIT2();
        __syncthreads();
        uint32_t base = sb + (it & 3) * STG64;
#pragma unroll
        for (int ks = 0; ks < 4; ks++) {
            uint32_t af[2][4], bfr[2][4];
#pragma unroll
            for (int mt = 0; mt < 2; mt++) ldsm4(af[mt], base + aoff[mt] + ks * 32);
#pragma unroll
            for (int np = 0; np < 2; np++) ldsm4(bfr[np], base + boff[np] + ks * 32);
#pragma unroll
            for (int mt = 0; mt < 2; mt++) {
#pragma unroll
                for (int nt = 0; nt < 4; nt++)
                    mma16816(acc[mt][nt], af[mt], bfr[nt >> 1][(nt & 1) * 2],
                             bfr[nt >> 1][(nt & 1) * 2 + 1]);
            }
        }
        if (it + 3 < NIT) issue(it + 3);
        CP_COMMIT();
    }

    const int er = lane >> 2, ec = (lane & 3) * 2;
#pragma unroll
    for (int mt = 0; mt < 2; mt++) {
#pragma unroll
        for (int nt = 0; nt < 4; nt++) {
            int m0 = bm + wm + mt * 16 + er;
            int n0 = bn + wn + nt * 8 + ec;
            float* a = acc[mt][nt];
            float b0 = biasp[n0], b1 = biasp[n0 + 1];
            float2 v0 = {a[0] + b0, a[1] + b1};
            float2 v1 = {a[2] + b0, a[3] + b1};
            *(float2*)(Cf + (size_t)m0 * ldc + n0) = v0;
            *(float2*)(Cf + (size_t)(m0 + 8) * ldc + n0) = v1;
        }
    }
}

// ============ tg32: tile 64x32, 64 thr (scan GEMMs) ============
#define PL32  9216
#define STG32 13824
#define DS32 (4 * STG32)

template <int MODE>
__global__ void __launch_bounds__(64, 4) tg32(
    const f16* __restrict__ A0c, const f16* __restrict__ A1c, int lda,
    const f16* __restrict__ W0c, const f16* __restrict__ W1c, int K,
    float* __restrict__ Cf, f16* __restrict__ C0, f16* __restrict__ C1, int ldc,
    const float* __restrict__ bias, const float* __restrict__ bias2,
    const float* __restrict__ aux) {
    extern __shared__ char smem[];
    const uint32_t sb = smem_u32(smem);
    const int tid = threadIdx.x, wid = tid >> 5, lane = tid & 31;
    const int bn = blockIdx.x * 32, bm = blockIdx.y * 64;

    const f16* A0 = A0c; const f16* A1 = A1c;
    const float* biasp = bias;
    if (MODE == 0 && bias2 != nullptr && bn >= 1024) {
        A0 += 1024; A1 += 1024; biasp = bias2 - 1024;
    }
    const f16* Ap[2] = {A0 + (size_t)bm * lda, A1 + (size_t)bm * lda};
    const f16* Wp[2] = {W0c + (size_t)bn * K, W1c + (size_t)bn * K};

    const int nk = K >> 6;
    const int NIT = 3 * nk;
    const int tA[3] = {0, 0, 1};
    const int tB[3] = {0, 1, 0};

    const int lr = tid >> 3, lc = tid & 7;
    const int wm = wid * 32;

    uint32_t aoff[2], boff[2];
#pragma unroll
    for (int mt = 0; mt < 2; mt++)
        aoff[mt] = (uint32_t)(wm + mt * 16 + (lane & 7) + ((lane >> 3) & 1) * 8) * 144
                 + ((lane >> 4) & 1) * 16;
#pragma unroll
    for (int np = 0; np < 2; np++)
        boff[np] = PL32 + (uint32_t)(np * 16 + (lane & 7) + ((lane >> 4) & 1) * 8) * 144
                 + ((lane >> 3) & 1) * 16;

    float acc[2][4][4];
#pragma unroll
    for (int i = 0; i < 2; i++)
#pragma unroll
        for (int j = 0; j < 4; j++)
#pragma unroll
            for (int q = 0; q < 4; q++) acc[i][j][q] = 0.0f;

    auto issue = [&](int chunk) {
        int term = chunk / nk, kc = chunk - term * nk;
        const f16* As = Ap[tA[term]] + kc * 64;
        const f16* Ws = Wp[tB[term]] + kc * 64;
        uint32_t st = sb + (chunk & 3) * STG32;
#pragma unroll
        for (int i = 0; i < 8; i++) {
            int row = lr + i * 8;
            cp16(st + row * 144 + lc * 16, As + (size_t)row * lda + lc * 8);
        }
#pragma unroll
        for (int i = 0; i < 4; i++) {
            int row = lr + i * 8;
            cp16(st + PL32 + row * 144 + lc * 16, Ws + (size_t)row * K + lc * 8);
        }
    };

    issue(0); CP_COMMIT();
    issue(1); CP_COMMIT();
    issue(2); CP_COMMIT();

    for (int it = 0; it < NIT; it++) {
        CP_WAIT2();
        __syncthreads();
        uint32_t base = sb + (it & 3) * STG32;
#pragma unroll
        for (int ks = 0; ks < 4; ks++) {
            uint32_t af[2][4], bfr[2][4];
#pragma unroll
            for (int mt = 0; mt < 2; mt++) ldsm4(af[mt], base + aoff[mt] + ks * 32);
#pragma unroll
            for (int np = 0; np < 2; np++) ldsm4(bfr[np], base + boff[np] + ks * 32);
#pragma unroll
            for (int mt = 0; mt < 2; mt++) {
#pragma unroll
                for (int nt = 0; nt < 4; nt++)
                    mma16816(acc[mt][nt], af[mt], bfr[nt >> 1][(nt & 1) * 2],
                             bfr[nt >> 1][(nt & 1) * 2 + 1]);
            }
        }
        if (it + 3 < NIT) issue(it + 3);
        CP_COMMIT();
    }

    const int er = lane >> 2, ec = (lane & 3) * 2;
#pragma unroll
    for (int mt = 0; mt < 2; mt++) {
#pragma unroll
        for (int nt = 0; nt < 4; nt++) {
            int m0 = bm + wm + mt * 16 + er;
            int n0 = bn + nt * 8 + ec;
            float* a = acc[mt][nt];
            if (MODE == 0) {
                float b0 = biasp[n0], b1 = biasp[n0 + 1];
                float2 v0 = {a[0] + b0, a[1] + b1};
                float2 v1 = {a[2] + b0, a[3] + b1};
                *(float2*)(Cf + (size_t)m0 * ldc + n0) = v0;
                *(float2*)(Cf + (size_t)(m0 + 8) * ldc + n0) = v1;
            } else {
                const bool left = (bn < 1024);
#pragma unroll
                for (int rr = 0; rr < 2; rr++) {
                    int m = m0 + rr * 8;
                    float ad0 = left ? bias[n0]     : aux[(size_t)m * 1024 + n0 - 1024];
                    float ad1 = left ? bias[n0 + 1] : aux[(size_t)m * 1024 + n0 + 1 - 1024];
                    float v0 = siluf(a[rr * 2 + 0] + ad0);
                    float v1 = siluf(a[rr * 2 + 1] + ad1);
                    f16 h0, l0, h1, l1;
                    split2(v0, h0, l0);
                    split2(v1, h1, l1);
                    *(__half2*)(C0 + (size_t)m * ldc + n0) = __halves2half2(h0, h1);
                    *(__half2*)(C1 + (size_t)m * ldc + n0) = __halves2half2(l0, l1);
                }
            }
        }
    }
}

// ============ SIMT fp32 GEMM (prep + step0) ============
#define BM 64
#define BN 64
#define BKT 16
template <int MODE>
__global__ void gemm_k(const float* __restrict__ A, int lda,
                       const float* __restrict__ W, int ldw,
                       float* __restrict__ C, int ldc, int K,
                       const float* __restrict__ bias,
                       const float* __restrict__ aux, int auxld) {
    __shared__ float As[BKT][BM + 4];
    __shared__ float Bs[BKT][BN];
    const int bn = blockIdx.x * BN, bm = blockIdx.y * BM, tid = threadIdx.x;
    const int tx = tid & 15, ty = tid >> 4;
    const int arow = tid >> 2, avec = tid & 3;
    const int wrow = tid >> 4, wvec = tid & 15;
    float acc[4][4];
#pragma unroll
    for (int i = 0; i < 4; i++)
#pragma unroll
        for (int j = 0; j < 4; j++) acc[i][j] = 0.0f;
    for (int k0 = 0; k0 < K; k0 += BKT) {
        float4 a4 = *(const float4*)(A + (size_t)(bm + arow) * lda + k0 + avec * 4);
        As[avec * 4 + 0][arow] = a4.x;
        As[avec * 4 + 1][arow] = a4.y;
        As[avec * 4 + 2][arow] = a4.z;
        As[avec * 4 + 3][arow] = a4.w;
        *(float4*)&Bs[wrow][wvec * 4] =
            *(const float4*)(W + (size_t)(k0 + wrow) * ldw + bn + wvec * 4);
        __syncthreads();
#pragma unroll
        for (int k = 0; k < BKT; k++) {
            float4 ar = *(const float4*)&As[k][ty * 4];
            float4 br = *(const float4*)&Bs[k][tx * 4];
            acc[0][0] += ar.x * br.x; acc[0][1] += ar.x * br.y;
            acc[0][2] += ar.x * br.z; acc[0][3] += ar.x * br.w;
            acc[1][0] += ar.y * br.x; acc[1][1] += ar.y * br.y;
            acc[1][2] += ar.y * br.z; acc[1][3] += ar.y * br.w;
            acc[2][0] += ar.z * br.x; acc[2][1] += ar.z * br.y;
            acc[2][2] += ar.z * br.z; acc[2][3] += ar.z * br.w;
            acc[3][0] += ar.w * br.x; acc[3][1] += ar.w * br.y;
            acc[3][2] += ar.w * br.z; acc[3][3] += ar.w * br.w;
        }
        __syncthreads();
    }
#pragma unroll
    for (int i = 0; i < 4; i++) {
        int m = bm + ty * 4 + i;
#pragma unroll
        for (int j = 0; j < 4; j++) {
            int gn = bn + tx * 4 + j;
            float v = acc[i][j];
            if (MODE == 0) { if (bias) v += bias[gn]; }
            else           { v = siluf(v + aux[(size_t)m * auxld + gn]); }
            C[(size_t)m * ldc + gn] = v;
        }
    }
}

// ============ prep / elementwise ============
__global__ void k_aproj(const float* __restrict__ actions, const float* __restrict__ Wi1,
                        const float* __restrict__ bi1, float* __restrict__ out) {
    int idx = blockIdx.x * 256 + threadIdx.x;
    int r = idx >> 10, j = idx & 1023;
    const float* act = actions + (size_t)r * 6;
    float acc = bi1[j];
#pragma unroll
    for (int q = 0; q < 6; q++) acc += act[q] * Wi1[(size_t)(1024 + q) * 1024 + j];
    out[idx] = acc;
}
__global__ void k_split2(const float* __restrict__ src, f16* __restrict__ d0,
                         f16* __restrict__ d1) {
    size_t i = (size_t)blockIdx.x * 256 + threadIdx.x;
    split2(src[i], d0[i], d1[i]);
}
__global__ void k_tsplit(const float* __restrict__ src, int srcRows, int srcCols,
                         f16* __restrict__ d0, f16* __restrict__ d1) {
    __shared__ float tile[32][33];
    int n0 = blockIdx.x * 32, k0 = blockIdx.y * 32;
    int tx = threadIdx.x, ty = threadIdx.y;
#pragma unroll
    for (int i = 0; i < 4; i++) {
        int k = k0 + ty + i * 8;
        tile[ty + i * 8][tx] = src[(size_t)k * srcCols + n0 + tx];
    }
    __syncthreads();
#pragma unroll
    for (int i = 0; i < 4; i++) {
        int n = n0 + ty + i * 8;
        float v = tile[tx][ty + i * 8];
        size_t o = (size_t)n * srcRows + k0 + tx;
        split2(v, d0[o], d1[o]);
    }
}
__global__ void k_bfold(const float* __restrict__ bi2, const float* __restrict__ Wg,
                        float* __restrict__ bf) {
    int n = blockIdx.x * 256 + threadIdx.x;
    if (n >= 3072) return;
    float acc = 0.0f;
    for (int k = 0; k < 1024; k++) acc += bi2[k] * Wg[(size_t)k * 3072 + n];
    bf[n] = acc;
}
__global__ void k_copy_wg_bot(const float* __restrict__ Wg, float* __restrict__ Wbig) {
    size_t idx = (size_t)blockIdx.x * 256 + threadIdx.x;
    Wbig[(size_t)1024 * 3072 + idx] = Wg[(size_t)1024 * 3072 + idx];
}
__global__ void k_initb(const float* __restrict__ b0, float* __restrict__ bstate,
                        f16* __restrict__ A0, f16* __restrict__ A1) {
    int idx = blockIdx.x * 256 + threadIdx.x;
    int m = idx >> 10, j = idx & 1023;
    float v = b0[idx];
    bstate[idx] = v;
    size_t o = (size_t)m * 2048 + 1024 + j;
    split2(v, A0[o], A1[o]);
}
__global__ void k_cvt_h1(const float* __restrict__ src, f16* __restrict__ A0,
                         f16* __restrict__ A1) {
    int idx = blockIdx.x * 256 + threadIdx.x;
    int m = idx >> 10, j = idx & 1023;
    size_t o = (size_t)m * 2048 + j;
    split2(src[idx], A0[o], A1[o]);
}
__global__ void k_ln_gru(const float* __restrict__ G, const float* __restrict__ ls,
                         const float* __restrict__ lb, float* __restrict__ bstate,
                         f16* __restrict__ A0, f16* __restrict__ A1) {
    int row = blockIdx.x, tid = threadIdx.x;
    const float* g = G + (size_t)row * 3072;
    __shared__ float red[256];
    __shared__ float mu_s, inv_s;
    float s = 0.0f;
    for (int j = tid; j < 3072; j += 256) s += g[j];
    red[tid] = s; __syncthreads();
    for (int o = 128; o > 0; o >>= 1) { if (tid < o) red[tid] += red[tid + o]; __syncthreads(); }
    if (tid == 0) mu_s = red[0] * (1.0f / 3072.0f);
    __syncthreads();
    float mu = mu_s;
    s = 0.0f;
    for (int j = tid; j < 3072; j += 256) { float d = g[j] - mu; s += d * d; }
    red[tid] = s; __syncthreads();
    for (int o = 128; o > 0; o >>= 1) { if (tid < o) red[tid] += red[tid + o]; __syncthreads(); }
    if (tid == 0) inv_s = 1.0f / sqrtf(red[0] * (1.0f / 3072.0f) + 1e-3f);
    __syncthreads();
    float inv = inv_s;
    float* b = bstate + (size_t)row * 1024;
    for (int j = tid; j < 1024; j += 256) {
        float r = (g[j]        - mu) * inv * ls[j]        + lb[j];
        float c = (g[1024 + j] - mu) * inv * ls[1024 + j] + lb[1024 + j];
        float u = (g[2048 + j] - mu) * inv * ls[2048 + j] + lb[2048 + j];
        float reset = sigm(r);
        float cand  = tanhf(reset * c);
        float upd   = sigm(u - 1.0f);
        float bn2 = upd * cand + (1.0f - upd) * b[j];
        b[j] = bn2;
        size_t o = (size_t)row * 2048 + 1024 + j;
        split2(bn2, A0[o], A1[o]);
    }
}
__device__ __forceinline__ float wmax(float v) {
#pragma unroll
    for (int o = 16; o > 0; o >>= 1) v = fmaxf(v, __shfl_xor_sync(0xffffffffu, v, o));
    return v;
}
__device__ __forceinline__ float wsum(float v) {
#pragma unroll
    for (int o = 16; o > 0; o >>= 1) v += __shfl_xor_sync(0xffffffffu, v, o);
    return v;
}
__global__ void k_head_z(const float* __restrict__ lg, const float* __restrict__ un,
                         float* __restrict__ out,
                         const float* __restrict__ Wi1, const float* __restrict__ Aproj_n,
                         int do_z, f16* __restrict__ A0, f16* __restrict__ A1) {
    int row = blockIdx.x, tid = threadIdx.x;
    int lane = tid & 31, w = tid >> 5;
    __shared__ float klp[32];
    __shared__ int idxs[32];
    const float* base = lg + (size_t)row * 2048;
    for (int sg = w; sg < 32; sg += 8) {
        float pl = base[sg * 32 + lane];
        pl = fminf(fmaxf(pl, -20.0f), 20.0f);
        float e = expf(pl - wmax(pl));
        float pp = e / wsum(e) * 0.99f + 0.0003125f;
        float ql = base[1024 + sg * 32 + lane];
        ql = fminf(fmaxf(ql, -20.0f), 20.0f);
        float e2 = expf(ql - wmax(ql));
        float qp = e2 / wsum(e2) * 0.99f + 0.0003125f;
        float kl = wsum(qp * (logf(qp + 1e-8f) - logf(pp + 1e-8f)));
        float u = un[(size_t)(row * 32 + sg) * 32 + lane];
        float gg = -logf(-logf(u + 1e-6f) + 1e-6f);
        float val = logf(fmaxf(qp, 1e-6f)) + gg;
        int idx = lane;
#pragma unroll
        for (int o = 16; o > 0; o >>= 1) {
            float ov = __shfl_down_sync(0xffffffffu, val, o);
            int   oi = __shfl_down_sync(0xffffffffu, idx, o);
            if (ov > val || (ov == val && oi < idx)) { val = ov; idx = oi; }
        }
        if (lane == 0) { klp[sg] = kl; idxs[sg] = sg * 32 + idx; }
    }
    __syncthreads();
    if (tid == 0) {
        float kl = 0.0f;
        for (int s = 0; s < 32; s++) kl += klp[s];
        out[row] = 1.1f * fmaxf(kl, 0.1f);
    }
    if (do_z) {
        for (int j = tid; j < 1024; j += 256) {
            float acc = Aproj_n[(size_t)row * 1024 + j];
#pragma unroll
            for (int s = 0; s < 32; s++) acc += Wi1[(size_t)idxs[s] * 1024 + j];
            float v = siluf(acc);
            size_t o = (size_t)row * 2048 + j;
            split2(v, A0[o], A1[o]);
        }
    }
}

// ============ launch ============
extern "C" void kernel_launch(void* const* d_in, const int* in_sizes, int n_in,
                              void* d_out, int out_size) {
    const float* b0      = (const float*)d_in[0];
    const float* z0      = (const float*)d_in[1];
    const float* actions = (const float*)d_in[2];
    const float* obs     = (const float*)d_in[3];
    const float* u_noise = (const float*)d_in[4];
    const float* Wi1     = (const float*)d_in[5];
    const float* bi1     = (const float*)d_in[6];
    const float* Wi2     = (const float*)d_in[7];
    const float* bi2     = (const float*)d_in[8];
    const float* Wg      = (const float*)d_in[9];
    const float* ln_s    = (const float*)d_in[10];
    const float* ln_b    = (const float*)d_in[11];
    const float* Wo1     = (const float*)d_in[12];
    const float* bo1     = (const float*)d_in[13];
    const float* Wo2     = (const float*)d_in[14];
    const float* bo2     = (const float*)d_in[15];
    const float* Wp1     = (const float*)d_in[16];
    const float* bp1     = (const float*)d_in[17];
    const float* Wp2     = (const float*)d_in[18];
    const float* bp2     = (const float*)d_in[19];
    float* out = (float*)d_out;

    float *Aproj, *Oproj, *Wbig, *bfold, *G, *lgp, *tmp, *bstate;
    f16 *ob0, *ob1, *Wo1T0, *Wo1T1, *WbT0, *WbT1;
    f16 *WcT0, *WcT1, *WlT0, *WlT1, *Ahb0, *Ahb1, *hq0, *hq1;
    cudaGetSymbolAddress((void**)&Aproj, g_Aproj);
    cudaGetSymbolAddress((void**)&Oproj, g_Oproj);
    cudaGetSymbolAddress((void**)&Wbig, g_Wbig);
    cudaGetSymbolAddress((void**)&bfold, g_bfold);
    cudaGetSymbolAddress((void**)&G, g_G);
    cudaGetSymbolAddress((void**)&lgp, g_lg);
    cudaGetSymbolAddress((void**)&tmp, g_tmp);
    cudaGetSymbolAddress((void**)&bstate, g_bstate);
    cudaGetSymbolAddress((void**)&ob0, g_obs0);
    cudaGetSymbolAddress((void**)&ob1, g_obs1);
    cudaGetSymbolAddress((void**)&Wo1T0, g_Wo1T0);
    cudaGetSymbolAddress((void**)&Wo1T1, g_Wo1T1);
    cudaGetSymbolAddress((void**)&WbT0, g_WbT0);
    cudaGetSymbolAddress((void**)&WbT1, g_WbT1);
    cudaGetSymbolAddress((void**)&WcT0, g_WcT0);
    cudaGetSymbolAddress((void**)&WcT1, g_WcT1);
    cudaGetSymbolAddress((void**)&WlT0, g_WlT0);
    cudaGetSymbolAddress((void**)&WlT1, g_WlT1);
    cudaGetSymbolAddress((void**)&Ahb0, g_Ahb0);
    cudaGetSymbolAddress((void**)&Ahb1, g_Ahb1);
    cudaGetSymbolAddress((void**)&hq0, g_hq0);
    cudaGetSymbolAddress((void**)&hq1, g_hq1);

    cudaFuncSetAttribute(tg64<0>, cudaFuncAttributeMaxDynamicSharedMemorySize, DS64);
    cudaFuncSetAttribute(tg32<0>, cudaFuncAttributeMaxDynamicSharedMemorySize, DS32);
    cudaFuncSetAttribute(tg32<3>, cudaFuncAttributeMaxDynamicSharedMemorySize, DS32);

    // second stream + events (created once, outside capture on the first call)
    static cudaStream_t sB = nullptr;
    static cudaEvent_t evFork, evPre, evOp[8];
    if (sB == nullptr) {
        cudaStreamCreateWithFlags(&sB, cudaStreamNonBlocking);
        cudaEventCreateWithFlags(&evFork, cudaEventDisableTiming);
        cudaEventCreateWithFlags(&evPre, cudaEventDisableTiming);
        for (int i = 0; i < 8; i++)
            cudaEventCreateWithFlags(&evOp[i], cudaEventDisableTiming);
    }

    // ---- fork stream B off the capture stream ----
    cudaEventRecord(evFork, 0);
    cudaStreamWaitEvent(sB, evFork, 0);

    // ---- stream B: independent prep + chunked Oproj ----
    k_aproj<<<T_STEPS * BATCH * 1024 / 256, 256, 0, sB>>>(actions, Wi1, bi1, Aproj);
    k_split2<<<T_STEPS * BATCH * 1024 / 256, 256, 0, sB>>>(obs, ob0, ob1);
    k_tsplit<<<dim3(32, 32), dim3(32, 8), 0, sB>>>(Wo1, 1024, 1024, Wo1T0, Wo1T1);
    k_tsplit<<<dim3(32, 32), dim3(32, 8), 0, sB>>>(Wp1, 1024, 1024, WcT0, WcT1);
    k_tsplit<<<dim3(32, 32), dim3(32, 8), 0, sB>>>(Wo1 + (size_t)1024 * 1024, 1024, 1024,
                                                   WcT0 + (size_t)1024 * 1024,
                                                   WcT1 + (size_t)1024 * 1024);
    k_tsplit<<<dim3(32, 32), dim3(32, 8), 0, sB>>>(Wp2, 1024, 1024, WlT0, WlT1);
    k_tsplit<<<dim3(32, 32), dim3(32, 8), 0, sB>>>(Wo2, 1024, 1024,
                                                   WlT0 + (size_t)1024 * 1024,
                                                   WlT1 + (size_t)1024 * 1024);
    cudaEventRecord(evPre, sB);
    // Oproj in 8 chunks of 8 timesteps (bit-identical tiles to one big launch)
    for (int c = 0; c < 8; c++) {
        size_t off = (size_t)c * 32 * 64 * 1024;  // 2048 rows per chunk
        tg64<0><<<dim3(16, 32), 128, DS64, sB>>>(ob0 + off, ob1 + off, 1024,
                                                 Wo1T0, Wo1T1, 1024,
                                                 Oproj + off, nullptr, nullptr, 1024,
                                                 bo1, nullptr, nullptr);
        cudaEventRecord(evOp[c], sB);
    }

    // ---- stream 0: Wbig chain + state init (critical path to gates(0)) ----
    gemm_k<0><<<dim3(3072 / BN, 1024 / BM), 256>>>(Wi2, 1024, Wg, 3072, Wbig, 3072, 1024,
                                                   nullptr, nullptr, 0);
    k_copy_wg_bot<<<1024 * 3072 / 256, 256>>>(Wg, Wbig);
    k_tsplit<<<dim3(96, 64), dim3(32, 8)>>>(Wbig, 2048, 3072, WbT0, WbT1);
    k_bfold<<<12, 256>>>(bi2, Wg, bfold);
    k_initb<<<BATCH * 1024 / 256, 256>>>(b0, bstate, Ahb0, Ahb1);
    gemm_k<1><<<dim3(1024 / BN, BATCH / BM), 256>>>(z0, 1024, Wi1, 1024, tmp, 1024,
                                                    1024, nullptr, Aproj, 1024);
    k_cvt_h1<<<BATCH * 1024 / 256, 256>>>(tmp, Ahb0, Ahb1);
    // join: head_z/hq need stream-B prep
    cudaStreamWaitEvent(0, evPre, 0);

    // ---- sequential scan ----
    for (int t = 0; t < T_STEPS; t++) {
        if ((t & 7) == 0) cudaStreamWaitEvent(0, evOp[t >> 3], 0);
        // gates = [h1|b] @ Wbig + bfold   (256 x 3072, K=2048) — 384 CTAs
        tg32<0><<<dim3(96, 4), 64, DS32>>>(Ahb0, Ahb1, 2048, WbT0, WbT1, 2048,
                                           G, nullptr, nullptr, 3072,
                                           bfold, nullptr, nullptr);
        k_ln_gru<<<BATCH, 256>>>(G, ln_s, ln_b, bstate, Ahb0, Ahb1);
        // hq = silu(b_new @ [Wp1|Wo1_bot] + {bp1 | Oproj[t]})  (256 x 2048, K=1024)
        tg32<3><<<dim3(64, 4), 64, DS32>>>(Ahb0 + 1024, Ahb1 + 1024, 2048,
                                           WcT0, WcT1, 1024,
                                           nullptr, hq0, hq1, 2048,
                                           bp1, nullptr, Oproj + (size_t)t * BATCH * 1024);
        // logits = [h_p @ Wp2 + bp2 | h_o @ Wo2 + bo2]  (256 x 2048, K=1024)
        tg32<0><<<dim3(64, 4), 64, DS32>>>(hq0, hq1, 2048, WlT0, WlT1, 1024,
                                           lgp, nullptr, nullptr, 2048,
                                           bp2, bo2, nullptr);
        // head + zgather(t+1)
        int do_z = (t + 1 < T_STEPS) ? 1 : 0;
        const float* apn = Aproj + (size_t)(do_z ? t + 1 : t) * BATCH * 1024;
        k_head_z<<<BATCH, 256>>>(lgp, u_noise + (size_t)t * BATCH * 1024,
                                 out + t * BATCH, Wi1, apn, do_z, Ahb0, Ahb1);
    }
}